// round 8
// baseline (speedup 1.0000x reference)
#include <cuda_runtime.h>
#include <cuda_fp16.h>
#include <cstdint>

// out[b] = -sum_ti Et[b][ti] * ( sum_zi Ez[b][zi] * (W[zi][ti]+eps) )
// prep: Ez (f16) and W' (f16) to gmem.  main: cp.async stage -> HMMA GEMM -> Et epilogue.

#define THREADS 256
#define BB 64
#define LDA 136                       // halves per smem row (272B): LDSM conflict-free

#define SMEM_A    0                                  // Ez:  64 x LDA f16 = 17408
#define SMEM_B    (BB * LDA * 2)                     // W': 128 x LDA f16 = 34816
#define SMEM_VEC  (SMEM_B + 128 * LDA * 2)           // tsh(64), tm(128)
#define SMEM_RED  (SMEM_VEC + (64 + 128) * 4)
#define SMEM_TOTAL (SMEM_RED + BB * 4 * 4)           // red: 64 rows x 4 wn

__device__ __half ez_g[16384 * 128];   // Ez[b][zi] row-major f16
__device__ __half w16_g[128 * 128];    // (weights+eps)[zi][ti] row-major f16

__device__ __forceinline__ void mma16816(float* d, const uint32_t* a,
                                         uint32_t b0, uint32_t b1) {
    asm volatile(
        "mma.sync.aligned.m16n8k16.row.col.f32.f16.f16.f32 "
        "{%0,%1,%2,%3}, {%4,%5,%6,%7}, {%8,%9}, {%0,%1,%2,%3};"
        : "+f"(d[0]), "+f"(d[1]), "+f"(d[2]), "+f"(d[3])
        : "r"(a[0]), "r"(a[1]), "r"(a[2]), "r"(a[3]), "r"(b0), "r"(b1));
}
__device__ __forceinline__ uint32_t smem_u32(const void* p) {
    uint32_t a;
    asm("{ .reg .u64 t; cvta.to.shared.u64 t, %1; cvt.u32.u64 %0, t; }" : "=r"(a) : "l"(p));
    return a;
}
__device__ __forceinline__ void ldsm_x4(uint32_t* r, uint32_t addr) {
    asm volatile("ldmatrix.sync.aligned.m8n8.x4.shared.b16 {%0,%1,%2,%3}, [%4];"
                 : "=r"(r[0]), "=r"(r[1]), "=r"(r[2]), "=r"(r[3]) : "r"(addr));
}
__device__ __forceinline__ void ldsm_x4_trans(uint32_t* r, uint32_t addr) {
    asm volatile("ldmatrix.sync.aligned.m8n8.x4.trans.shared.b16 {%0,%1,%2,%3}, [%4];"
                 : "=r"(r[0]), "=r"(r[1]), "=r"(r[2]), "=r"(r[3]) : "r"(addr));
}
__device__ __forceinline__ void cp16(uint32_t dst, const void* src) {
    asm volatile("cp.async.ca.shared.global [%0], [%1], 16;" :: "r"(dst), "l"(src) : "memory");
}

// ---------------- prep: Ez + W' in f16 ----------------
__global__ __launch_bounds__(256)
void prep_kernel(const float* __restrict__ z,
                 const float* __restrict__ means,
                 const float* __restrict__ weights) {
    __shared__ float zsh[64], zm[128];
    const int blk = blockIdx.x, tid = threadIdx.x;
    if (blk < 256) {
        if (tid < 64)  zsh[tid] = z[blk * 64 + tid];
        if (tid < 128) zm[tid] = means[tid * 256];   // means (Z,T,2): zm[zi]=means[zi][0][0]
        __syncthreads();
        const size_t base = (size_t)blk * 8192;
        #pragma unroll
        for (int it = 0; it < 16; it++) {
            int idx = it * 512 + tid * 2;            // b_local*128 + zi
            int b = idx >> 7, zi = idx & 127;
            float zb = zsh[b];
            float d0 = zb - zm[zi], d1 = zb - zm[zi + 1];
            __half2 h = __floats2half2_rn(__expf(-50.0f * d0 * d0),
                                          __expf(-50.0f * d1 * d1));
            *reinterpret_cast<__half2*>(ez_g + base + idx) = h;
        }
    } else {
        const int base = (blk - 256) * 8192;
        #pragma unroll
        for (int it = 0; it < 16; it++) {
            int idx = base + it * 512 + tid * 2;
            float2 wv = *reinterpret_cast<const float2*>(weights + idx);
            *reinterpret_cast<__half2*>(w16_g + idx) =
                __floats2half2_rn(wv.x + 0.01f, wv.y + 0.01f);
        }
    }
}

// ---------------- main: copy -> GEMM -> epilogue ----------------
__global__ __launch_bounds__(THREADS, 2)
void gkb_density_kernel(const float* __restrict__ t,
                        const float* __restrict__ means,
                        float* __restrict__ out) {
    extern __shared__ char smem[];
    __half* ash = reinterpret_cast<__half*>(smem + SMEM_A);   // Ez [b][zi], 64 rows
    __half* wsh = reinterpret_cast<__half*>(smem + SMEM_B);   // W' [zi][ti], 128 rows
    float* tsh = reinterpret_cast<float*>(smem + SMEM_VEC);   // 64
    float* tm  = tsh + 64;                                    // 128
    float* red = reinterpret_cast<float*>(smem + SMEM_RED);   // [64][4]

    const int tid = threadIdx.x;
    const int b0  = blockIdx.x * BB;

    // ---- stage A and B via cp.async (16B chunks into LDA=136 layout) ----
    {
        const uint32_t a_dst = smem_u32(ash);
        const char* a_src = reinterpret_cast<const char*>(ez_g + (size_t)b0 * 128);
        #pragma unroll
        for (int i = 0; i < 4; i++) {                // 1024 chunks
            int c = i * THREADS + tid;
            int row = c >> 4, col = (c & 15) << 4;
            cp16(a_dst + row * 272 + col, a_src + row * 256 + col);
        }
        const uint32_t b_dst = smem_u32(wsh);
        const char* b_src = reinterpret_cast<const char*>(w16_g);
        #pragma unroll
        for (int i = 0; i < 8; i++) {                // 2048 chunks
            int c = i * THREADS + tid;
            int row = c >> 4, col = (c & 15) << 4;
            cp16(b_dst + row * 272 + col, b_src + row * 256 + col);
        }
        asm volatile("cp.async.commit_group;" ::: "memory");
    }
    if (tid < 64)  tsh[tid] = t[b0 + tid];
    if (tid < 128) tm[tid] = means[tid * 2 + 1];     // tm[ti]=means[0][ti][1]
    asm volatile("cp.async.wait_group 0;" ::: "memory");
    __syncthreads();

    // ---- warp-tiled GEMM: 8 warps in 2(m) x 4(n), warp tile 32x32, K=128 ----
    const int lane = tid & 31, wid = tid >> 5;
    const int g = lane >> 2, tg = lane & 3;
    const int wm = wid >> 2, wn = wid & 3;
    const int m0 = wm * 32, n0 = wn * 32;

    const int lr = lane & 15, lc = lane >> 4;
    const uint32_t a_lane0 = smem_u32(&ash[(m0 + lr) * LDA + lc * 8]);
    const uint32_t b_lane0 = smem_u32(&wsh[lr * LDA + n0 + lc * 8]);

    float d[2][4][4];
    #pragma unroll
    for (int mt = 0; mt < 2; mt++)
        #pragma unroll
        for (int nt = 0; nt < 4; nt++)
            #pragma unroll
            for (int e = 0; e < 4; e++) d[mt][nt][e] = 0.0f;

    #pragma unroll
    for (int ks = 0; ks < 8; ks++) {
        uint32_t a[2][4], b[2][4];
        ldsm_x4(a[0], a_lane0 + ks * 32);
        ldsm_x4(a[1], a_lane0 + 16 * LDA * 2 + ks * 32);
        ldsm_x4_trans(b[0], b_lane0 + ks * 16 * LDA * 2);
        ldsm_x4_trans(b[1], b_lane0 + ks * 16 * LDA * 2 + 32);
        #pragma unroll
        for (int mt = 0; mt < 2; mt++)
            #pragma unroll
            for (int nb = 0; nb < 2; nb++) {
                mma16816(d[mt][nb * 2],     a[mt], b[nb][0], b[nb][1]);
                mma16816(d[mt][nb * 2 + 1], a[mt], b[nb][2], b[nb][3]);
            }
    }

    // ---- epilogue: fold Et, reduce over ti ----
    #pragma unroll
    for (int mt = 0; mt < 2; mt++) {
        #pragma unroll
        for (int h = 0; h < 2; h++) {
            const int row = m0 + mt * 16 + h * 8 + g;
            const float tb = tsh[row];
            float acc = 0.0f;
            #pragma unroll
            for (int nt = 0; nt < 4; nt++) {
                const int c0 = n0 + nt * 8 + tg * 2;
                float dt0 = tb - tm[c0];
                float dt1 = tb - tm[c0 + 1];
                acc += d[mt][nt][h * 2 + 0] * __expf(-50.0f * dt0 * dt0);
                acc += d[mt][nt][h * 2 + 1] * __expf(-50.0f * dt1 * dt1);
            }
            acc += __shfl_xor_sync(0xffffffffu, acc, 1);
            acc += __shfl_xor_sync(0xffffffffu, acc, 2);
            if (tg == 0) red[row * 4 + wn] = acc;
        }
    }
    __syncthreads();
    if (tid < BB) {
        const float* r = &red[tid * 4];
        out[b0 + tid] = -(r[0] + r[1] + r[2] + r[3]);
    }
}

extern "C" void kernel_launch(void* const* d_in, const int* in_sizes, int n_in,
                              void* d_out, int out_size) {
    const float* z       = (const float*)d_in[0];
    const float* t       = (const float*)d_in[1];
    const float* means   = (const float*)d_in[2];
    const float* weights = (const float*)d_in[3];
    float* out = (float*)d_out;

    cudaFuncSetAttribute(gkb_density_kernel,
                         cudaFuncAttributeMaxDynamicSharedMemorySize, SMEM_TOTAL);

    const int B = in_sizes[0];           // 16384
    prep_kernel<<<258, 256>>>(z, means, weights);
    gkb_density_kernel<<<B / BB, THREADS, SMEM_TOTAL>>>(t, means, out);
}